// round 4
// baseline (speedup 1.0000x reference)
#include <cuda_runtime.h>

// g_U[j][k] = (Re U[k][j], Im U[k][j]) : column j of the fixed 16x16 unitary
// implementing all 6 layers of Rot gates + CNOT rings.
__device__ __align__(16) float2 g_U[16][16];

__device__ __forceinline__ float2 cmul(float2 a, float2 b) {
    return make_float2(a.x * b.x - a.y * b.y, a.x * b.y + a.y * b.x);
}

// ---------------------------------------------------------------------------
// Prep: 512 threads. Threads 0..23 build the 24 gate matrices (precise
// sincosf) into shared. Then warp j (0..15) propagates basis vector e_j:
// lane k holds amplitude U[k][j]; 1-qubit gates via shfl_xor butterflies,
// CNOT permutations via computed-source shuffles. Fires the PDL trigger
// immediately so qmain's prologue can overlap.
// ---------------------------------------------------------------------------
__global__ void prep_kernel(const float* __restrict__ wts) {
    cudaTriggerProgrammaticLaunchCompletion();   // release qmain launch now

    __shared__ float2 sm[24][4];   // m00, m01, m10, m11 per gate
    int tid = threadIdx.x;
    if (tid < 24) {
        float ph = wts[tid * 3 + 0];
        float th = wts[tid * 3 + 1];
        float om = wts[tid * 3 + 2];
        float st, ct; sincosf(0.5f * th, &st, &ct);
        float sa, ca; sincosf(0.5f * (ph + om), &sa, &ca);
        float sb, cb; sincosf(0.5f * (ph - om), &sb, &cb);
        sm[tid][0] = make_float2( ca * ct, -sa * ct);   //  ep*c
        sm[tid][1] = make_float2(-cb * st, -sb * st);   // -conj(em)*s
        sm[tid][2] = make_float2( cb * st, -sb * st);   //  em*s
        sm[tid][3] = make_float2( ca * ct,  sa * ct);   //  conj(ep)*c
    }
    __syncthreads();

    int j    = tid >> 5;        // warp = column index
    int lane = tid & 31;
    int k    = lane & 15;       // amplitude index (halves of warp mirror)
    float2 v = make_float2(k == j ? 1.0f : 0.0f, 0.0f);

#pragma unroll
    for (int l = 0; l < 6; ++l) {
#pragma unroll
        for (int w = 0; w < 4; ++w) {
            int g = l * 4 + w;
            float2 m00 = sm[g][0], m01 = sm[g][1], m10 = sm[g][2], m11 = sm[g][3];
            int mask = 8 >> w;
            float px = __shfl_xor_sync(0xffffffffu, v.x, mask);
            float py = __shfl_xor_sync(0xffffffffu, v.y, mask);
            float2 p = make_float2(px, py);
            float2 cv = (k & mask) ? m11 : m00;
            float2 cp = (k & mask) ? m10 : m01;
            float2 a = cmul(cv, v), b = cmul(cp, p);
            v = make_float2(a.x + b.x, a.y + b.y);
        }
        int r = l % 3 + 1;
#pragma unroll
        for (int w = 0; w < 4; ++w) {
            int cmask = 8 >> w;
            int tmask = 8 >> ((w + r) & 3);
            int src = (k & cmask) ? (k ^ tmask) : k;
            src |= (lane & 16);
            float nx = __shfl_sync(0xffffffffu, v.x, src);
            float ny = __shfl_sync(0xffffffffu, v.y, src);
            v = make_float2(nx, ny);
        }
    }
    if (lane < 16) g_U[j][k] = v;
}

// ---------------------------------------------------------------------------
// Packed f32x2 helpers. Lane0 = real, lane1 = imag.
// ---------------------------------------------------------------------------
__device__ __forceinline__ unsigned long long splat2(float v) {
    unsigned long long r;
    asm("mov.b64 %0, {%1, %1};" : "=l"(r) : "f"(v));
    return r;
}
__device__ __forceinline__ void ffma2(unsigned long long& acc,
                                      unsigned long long a, unsigned long long b) {
    asm("fma.rn.f32x2 %0, %1, %2, %0;" : "+l"(acc) : "l"(a), "l"(b));
}
__device__ __forceinline__ float2 unpack2(unsigned long long v) {
    float2 r;
    asm("mov.b64 {%0, %1}, %2;" : "=f"(r.x), "=f"(r.y) : "l"(v));
    return r;
}

// ---------------------------------------------------------------------------
// Main: 4 batch elements/thread, processed as 2 pairs to keep live
// accumulators at 16 f32x2 (<=128 regs => occupancy 2 => grid of 256 CTAs
// fits in ONE wave). LDS.128 matrix loads, factored state (h[4] x l[4]),
// per-half sign-butterfly epilogue. PDL overlaps the prologue with prep.
// ---------------------------------------------------------------------------
__global__ __launch_bounds__(256, 2)
void qmain_kernel(const float4* __restrict__ x4, float4* __restrict__ out4, int quarter) {
    __shared__ float4 sU[16][8];  // sU[j][kk] = (Re U[2kk][j], Im, Re U[2kk+1][j], Im)
    int tid = threadIdx.x;
    int gtid = blockIdx.x * 256 + tid;

    // ---- prologue: independent of g_U (overlaps prep via PDL) ----
    float h[4][4], l[4][4];
#pragma unroll
    for (int e = 0; e < 4; ++e) {
        float4 xa = x4[gtid + e * quarter];
        float c0, s0, c1, s1, c2, s2, c3, s3;
        __sincosf(0.5f * xa.x, &s0, &c0);
        __sincosf(0.5f * xa.y, &s1, &c1);
        __sincosf(0.5f * xa.z, &s2, &c2);
        __sincosf(0.5f * xa.w, &s3, &c3);
        h[e][0] = c0 * c1; h[e][1] = c0 * s1; h[e][2] = s0 * c1; h[e][3] = s0 * s1;
        l[e][0] = c2 * c3; l[e][1] = c2 * s3; l[e][2] = s2 * c3; l[e][3] = s2 * s3;
    }

    // ---- wait for prep, then stage the unitary ----
    cudaGridDependencySynchronize();
    if (tid < 128) ((float4*)sU)[tid] = ((const float4*)g_U)[tid];
    __syncthreads();

    float q[4][4];
#pragma unroll
    for (int e = 0; e < 4; ++e)
#pragma unroll
        for (int i = 0; i < 4; ++i) q[e][i] = 0.f;

#pragma unroll
    for (int pr = 0; pr < 2; ++pr) {          // element pair: e = 2*pr + {0,1}
#pragma unroll
        for (int hp = 0; hp < 2; ++hp) {      // k half: k = hp*8 + kk, bit3 == hp
            unsigned long long acc[2][8];
#pragma unroll
            for (int u = 0; u < 2; ++u)
#pragma unroll
                for (int kk = 0; kk < 8; ++kk) acc[u][kk] = 0ull;

#pragma unroll
            for (int j = 0; j < 16; ++j) {
                unsigned long long sj0 = splat2(h[2 * pr][j >> 2] * l[2 * pr][j & 3]);
                unsigned long long sj1 = splat2(h[2 * pr + 1][j >> 2] * l[2 * pr + 1][j & 3]);
                const ulonglong2* row = reinterpret_cast<const ulonglong2*>(&sU[j][hp * 4]);
#pragma unroll
                for (int kk = 0; kk < 4; ++kk) {
                    ulonglong2 m = row[kk];            // LDS.128: 2 complex entries
                    ffma2(acc[0][2 * kk],     m.x, sj0);
                    ffma2(acc[0][2 * kk + 1], m.y, sj0);
                    ffma2(acc[1][2 * kk],     m.x, sj1);
                    ffma2(acc[1][2 * kk + 1], m.y, sj1);
                }
            }

            // epilogue for this half / pair
#pragma unroll
            for (int u = 0; u < 2; ++u) {
                int e = 2 * pr + u;
                float p[8];
#pragma unroll
                for (int kk = 0; kk < 8; ++kk) {
                    float2 v = unpack2(acc[u][kk]);
                    p[kk] = v.x * v.x + v.y * v.y;
                }
                float s01 = p[0] + p[1], d01 = p[0] - p[1];
                float s23 = p[2] + p[3], d23 = p[2] - p[3];
                float s45 = p[4] + p[5], d45 = p[4] - p[5];
                float s67 = p[6] + p[7], d67 = p[6] - p[7];
                float uu = s01 + s23, v2 = s45 + s67;
                float A = uu + v2;
                q[e][0] += hp ? -A : A;                  // bit3 = hp
                q[e][1] += uu - v2;                      // bit2
                q[e][2] += (s01 - s23) + (s45 - s67);    // bit1
                q[e][3] += (d01 + d23) + (d45 + d67);    // bit0
            }
        }
    }

#pragma unroll
    for (int e = 0; e < 4; ++e)
        out4[gtid + e * quarter] = make_float4(q[e][0], q[e][1], q[e][2], q[e][3]);
}

extern "C" void kernel_launch(void* const* d_in, const int* in_sizes, int n_in,
                              void* d_out, int out_size) {
    const float* x   = (const float*)d_in[0];
    const float* wts = (const float*)d_in[1];
    int nx = in_sizes[0];
    if (n_in >= 2 && in_sizes[0] == 72 && in_sizes[1] != 72) {
        wts = (const float*)d_in[0];
        x   = (const float*)d_in[1];
        nx  = in_sizes[1];
    }
    int B = nx / 4;              // 262144
    int quarter = B / 4;         // 4 elems/thread
    int grid = (quarter + 255) / 256;   // 256 CTAs -> single wave at occ 2

    prep_kernel<<<1, 512>>>(wts);

    // PDL launch: qmain's prologue overlaps prep (prep triggers early);
    // cudaGridDependencySynchronize gates the g_U read on prep completion.
    cudaLaunchConfig_t cfg = {};
    cfg.gridDim  = dim3((unsigned)grid, 1, 1);
    cfg.blockDim = dim3(256, 1, 1);
    cfg.dynamicSmemBytes = 0;
    cfg.stream = 0;
    cudaLaunchAttribute attrs[1];
    attrs[0].id = cudaLaunchAttributeProgrammaticStreamSerialization;
    attrs[0].val.programmaticStreamSerializationAllowed = 1;
    cfg.attrs = attrs;
    cfg.numAttrs = 1;
    cudaLaunchKernelEx(&cfg, qmain_kernel, (const float4*)x, (float4*)d_out, quarter);
}